// round 4
// baseline (speedup 1.0000x reference)
#include <cuda_runtime.h>
#include <cuda_bf16.h>

#define Bq 256
#define Tq 512
#define Kq 128
#define SOS 0
#define EOSI 1
#define NSM 152   // GB300 SMs; wave-2 CTA (bid+152) co-resides with bid

__device__ float g_E[Kq * Kq];   // exp(trans), row-major
__device__ int   g_perm[Bq];     // batch index sorted by descending length

// ---------------- prep: E = exp(trans)  AND  length-rank permutation ----------------
__global__ void prep_kernel(const float* __restrict__ trans,
                            const float* __restrict__ mask) {
    if (blockIdx.x < 64) {
        int i = blockIdx.x * 256 + threadIdx.x;
        g_E[i] = expf(trans[i]);          // exp(-10000) -> exactly 0
    } else {
        __shared__ int slen[Bq];
        int tid = threadIdx.x, w = tid >> 5, lane = tid & 31;
        for (int r = w; r < Bq; r += 8) {
            float s = 0.f;
            const float* mr = mask + (size_t)r * Tq;
            for (int i = lane; i < Tq; i += 32) s += mr[i];
            #pragma unroll
            for (int o = 16; o > 0; o >>= 1) s += __shfl_xor_sync(0xffffffffu, s, o);
            if (lane == 0) slen[r] = (int)(s + 0.5f);
        }
        __syncthreads();
        int L = slen[tid];
        int rank = 0;
        for (int j = 0; j < Bq; j++) {
            int Lj = slen[j];
            rank += (Lj > L) || (Lj == L && j < tid);
        }
        g_perm[rank] = tid;
    }
}

__device__ __forceinline__ unsigned long long pk2(float a, float b) {
    return (unsigned long long)__float_as_uint(a) |
           ((unsigned long long)__float_as_uint(b) << 32);
}
__device__ __forceinline__ void fma2(unsigned long long& d,
                                     unsigned long long a, unsigned long long b) {
    asm("fma.rn.f32x2 %0, %1, %2, %0;" : "+l"(d) : "l"(a), "l"(b));
}
__device__ __forceinline__ void add2(unsigned long long& d, unsigned long long a) {
    asm("add.rn.f32x2 %0, %0, %1;" : "+l"(d) : "l"(a));
}
__device__ __forceinline__ float warp_max_pos(float v) {
    unsigned u = __float_as_uint(v), r;
    asm("redux.sync.max.u32 %0, %1, 0xffffffff;" : "=r"(r) : "r"(u));
    return __uint_as_float(r);     // valid for non-negative floats
}

// ---------------- main CRF scan: 256 threads, 2 threads per output row ----------------
__global__ void __launch_bounds__(256, 2) crf_main_kernel(
    const float* __restrict__ h, const float* __restrict__ mask,
    float* __restrict__ out)
{
    int bid = blockIdx.x;
    // Scheduling: solo SMs (bids 104..151, no wave-2 partner) take the 48
    // longest sequences; pair (i, i+152) takes complementary ranks.
    int rank;
    if (bid >= 104 && bid < NSM) rank = bid - 104;          // ranks 0..47 solo
    else if (bid < 104)          rank = 48 + bid;           // 48..151
    else                         rank = 407 - bid;          // 255..152
    int b = g_perm[rank] & (Bq - 1);

    int tid  = threadIdx.x;
    int w    = tid >> 5, lane = tid & 31;
    int row  = w * 16 + (lane >> 1);   // output row this thread works on
    int half = lane & 1;               // which 64-wide half of E[row,:]

    __shared__ __align__(16) float pbuf[2][Kq];
    __shared__ float wred[2][8];

    // 32 packed f32x2 registers: E[row, half*64 .. half*64+63]
    unsigned long long e2[32];
    {
        const float4* er = reinterpret_cast<const float4*>(g_E + row * Kq + half * 64);
        #pragma unroll
        for (int i = 0; i < 16; i++) {
            float4 f = er[i];
            e2[2 * i]     = pk2(f.x, f.y);
            e2[2 * i + 1] = pk2(f.z, f.w);
        }
    }

    if (tid < Kq) pbuf[0][tid] = (tid == SOS) ? 1.0f : 0.0f;
    float C = 0.0f;          // applied log-offset
    float rinv = 1.0f;       // pending 1/mx
    float pend = 0.0f;       // pending log(mx)

    const float* hb = h + (size_t)b * Tq * Kq + row;   // both lanes of a pair load same h
    const float* mb = mask + (size_t)b * Tq;
    float eh   = __expf(hb[0]);
    float mcur = mb[0];
    __syncthreads();

    int t = 0;
    for (; t < Tq; t++) {
        if (mcur == 0.0f) break;             // prefix mask -> frozen afterwards

        float hnext = 0.f, mnext = 0.f;
        if (t + 1 < Tq) { hnext = hb[(size_t)(t + 1) * Kq]; mnext = mb[t + 1]; }
        float ehnext = __expf(hnext);

        eh *= rinv;                          // deferred normalization
        C  += pend;

        // half-dot: sum over 64 of E[row,j]*p[j]
        unsigned long long acc[8];
        #pragma unroll
        for (int i = 0; i < 8; i++) acc[i] = 0ull;
        const ulonglong2* pu =
            reinterpret_cast<const ulonglong2*>(pbuf[t & 1] + half * 64);
        #pragma unroll
        for (int i = 0; i < 16; i++) {
            ulonglong2 q = pu[i];
            fma2(acc[(2 * i) & 7],     e2[2 * i],     q.x);
            fma2(acc[(2 * i + 1) & 7], e2[2 * i + 1], q.y);
        }
        add2(acc[0], acc[4]); add2(acc[1], acc[5]);
        add2(acc[2], acc[6]); add2(acc[3], acc[7]);
        add2(acc[0], acc[2]); add2(acc[1], acc[3]);
        add2(acc[0], acc[1]);
        float s = __uint_as_float((unsigned)acc[0]) +
                  __uint_as_float((unsigned)(acc[0] >> 32));
        // combine halves within the lane pair (both lanes end with full v)
        float v = (s + __shfl_xor_sync(0xffffffffu, s, 1)) * eh;

        if (half == 0) pbuf[(t + 1) & 1][row] = v;   // write RAW

        float wm = warp_max_pos(v);          // max over this warp's 16 rows
        if (lane == 0) wred[t & 1][w] = wm;
        __syncthreads();                     // the ONLY barrier per step

        float mx = fmaxf(fmaxf(fmaxf(wred[t & 1][0], wred[t & 1][1]),
                               fmaxf(wred[t & 1][2], wred[t & 1][3])),
                         fmaxf(fmaxf(wred[t & 1][4], wred[t & 1][5]),
                               fmaxf(wred[t & 1][6], wred[t & 1][7])));
        rinv = 1.0f / mx;                    // consumed next step only
        pend = __logf(mx);

        eh = ehnext; mcur = mnext;
    }

    // out[b] = C + log( sum_k p_raw[k] * E[EOS,k] )  (last pend/rinv discarded)
    __syncthreads();
    float val = 0.f;
    if (tid < Kq) val = pbuf[t & 1][tid] * g_E[EOSI * Kq + tid];
    #pragma unroll
    for (int o = 16; o > 0; o >>= 1)
        val += __shfl_xor_sync(0xffffffffu, val, o);
    if (lane == 0 && w < 4) wred[0][w] = val;
    __syncthreads();
    if (tid == 0)
        out[b] = C + __logf(wred[0][0] + wred[0][1] + wred[0][2] + wred[0][3]);
}

extern "C" void kernel_launch(void* const* d_in, const int* in_sizes, int n_in,
                              void* d_out, int out_size) {
    const float* h     = (const float*)d_in[0];
    const float* trans = (const float*)d_in[1];
    const float* mask  = (const float*)d_in[2];
    float* out = (float*)d_out;
    (void)in_sizes; (void)n_in; (void)out_size;

    prep_kernel<<<65, 256>>>(trans, mask);
    crf_main_kernel<<<Bq, 256>>>(h, mask, out);
}

// round 5
// speedup vs baseline: 1.3420x; 1.3420x over previous
#include <cuda_runtime.h>
#include <cuda_bf16.h>

#define Bq 256
#define Tq 512
#define Kq 128
#define SOS 0
#define EOSI 1
#define NSM 152   // GB300 SMs; wave-2 CTA (bid+152) co-resides with bid
#define PF  4     // h/mask prefetch depth (steps)

__device__ float g_E[Kq * Kq];   // exp(trans), row-major
__device__ int   g_perm[Bq];     // batch index sorted by descending length

// ---------------- prep: E = exp(trans)  AND  length-rank permutation ----------------
__global__ void prep_kernel(const float* __restrict__ trans,
                            const float* __restrict__ mask) {
    if (blockIdx.x < 64) {
        int i = blockIdx.x * 256 + threadIdx.x;
        g_E[i] = expf(trans[i]);          // exp(-10000) -> exactly 0
    } else {
        __shared__ int slen[Bq];
        int tid = threadIdx.x, w = tid >> 5, lane = tid & 31;
        for (int r = w; r < Bq; r += 8) {
            float s = 0.f;
            const float* mr = mask + (size_t)r * Tq;
            for (int i = lane; i < Tq; i += 32) s += mr[i];
            #pragma unroll
            for (int o = 16; o > 0; o >>= 1) s += __shfl_xor_sync(0xffffffffu, s, o);
            if (lane == 0) slen[r] = (int)(s + 0.5f);
        }
        __syncthreads();
        int L = slen[tid];
        int rank = 0;
        for (int j = 0; j < Bq; j++) {
            int Lj = slen[j];
            rank += (Lj > L) || (Lj == L && j < tid);
        }
        g_perm[rank] = tid;
    }
}

__device__ __forceinline__ unsigned long long pk2(float a, float b) {
    return (unsigned long long)__float_as_uint(a) |
           ((unsigned long long)__float_as_uint(b) << 32);
}
__device__ __forceinline__ void fma2(unsigned long long& d,
                                     unsigned long long a, unsigned long long b) {
    asm("fma.rn.f32x2 %0, %1, %2, %0;" : "+l"(d) : "l"(a), "l"(b));
}
__device__ __forceinline__ void add2(unsigned long long& d, unsigned long long a) {
    asm("add.rn.f32x2 %0, %0, %1;" : "+l"(d) : "l"(a));
}
__device__ __forceinline__ float warp_max_pos(float v) {
    unsigned u = __float_as_uint(v), r;
    asm("redux.sync.max.u32 %0, %1, 0xffffffff;" : "=r"(r) : "r"(u));
    return __uint_as_float(r);     // valid for non-negative floats
}

// ---------------- main CRF scan: 128 threads, 1 thread per output row ----------------
__global__ void __launch_bounds__(128, 2) crf_main_kernel(
    const float* __restrict__ h, const float* __restrict__ mask,
    float* __restrict__ out)
{
    int bid = blockIdx.x;
    // Solo SMs (bids 104..151 have no wave-2 partner) take the 48 longest
    // sequences; pair (i, i+152) takes complementary length ranks.
    int rank;
    if (bid >= 104 && bid < NSM) rank = bid - 104;          // ranks 0..47 solo
    else if (bid < 104)          rank = 48 + bid;           // 48..151
    else                         rank = 407 - bid;          // 255..152
    int b = g_perm[rank] & (Bq - 1);

    int k = threadIdx.x;
    int lane = k & 31, w = k >> 5;

    __shared__ __align__(16) float pbuf[2][Kq];
    __shared__ float wred[2][4];

    // thread k owns E row k in registers, packed for f32x2
    unsigned long long e2[Kq / 2];
    {
        const float4* er = reinterpret_cast<const float4*>(g_E + k * Kq);
        #pragma unroll
        for (int i = 0; i < Kq / 4; i++) {
            float4 f = er[i];
            e2[2 * i]     = pk2(f.x, f.y);
            e2[2 * i + 1] = pk2(f.z, f.w);
        }
    }

    pbuf[0][k] = (k == SOS) ? 1.0f : 0.0f;
    float C = 0.0f;          // applied log-offset
    float rinv = 1.0f;       // pending 1/mx
    float pend = 0.0f;       // pending log(mx)

    const float* hb = h + (size_t)b * Tq * Kq + k;
    const float* mb = mask + (size_t)b * Tq;

    // 4-deep prefetch queues (MLP=4 covers DRAM latency ~600cyc << 4 steps)
    float hq[PF], mq[PF];
    #pragma unroll
    for (int i = 0; i < PF; i++) {
        hq[i] = (i < Tq) ? hb[(size_t)i * Kq] : 0.f;
        mq[i] = (i < Tq) ? mb[i] : 0.f;
    }
    float eh = __expf(hq[0]);     // eh for step 0, ready before loop
    __syncthreads();

    int t = 0;
    for (; t < Tq; t++) {
        if (mq[t & (PF - 1)] == 0.0f) break;   // prefix mask -> frozen afterwards

        // refill queue slot (consumed this step) with step t+PF
        int tp = t + PF;
        float hnew = 0.f, mnew = 0.f;
        if (tp < Tq) { hnew = hb[(size_t)tp * Kq]; mnew = mb[tp]; }

        // eh for NEXT step: source register loaded >=3 steps ago, ready now
        float ehnext = __expf(hq[(t + 1) & (PF - 1)]);

        hq[t & (PF - 1)] = hnew;
        mq[t & (PF - 1)] = mnew;

        // apply deferred normalization from previous step
        eh *= rinv;
        C  += pend;

        // dot[k] = sum_j E[k,j] * p[j], packed f32x2, 8 accumulators
        unsigned long long acc[8];
        #pragma unroll
        for (int i = 0; i < 8; i++) acc[i] = 0ull;
        const ulonglong2* pu = reinterpret_cast<const ulonglong2*>(pbuf[t & 1]);
        #pragma unroll
        for (int i = 0; i < Kq / 4; i++) {
            ulonglong2 q = pu[i];            // broadcast LDS.128, conflict-free
            fma2(acc[(2 * i) & 7],     e2[2 * i],     q.x);
            fma2(acc[(2 * i + 1) & 7], e2[2 * i + 1], q.y);
        }
        add2(acc[0], acc[4]); add2(acc[1], acc[5]);
        add2(acc[2], acc[6]); add2(acc[3], acc[7]);
        add2(acc[0], acc[2]); add2(acc[1], acc[3]);
        add2(acc[0], acc[1]);
        float v = (__uint_as_float((unsigned)acc[0]) +
                   __uint_as_float((unsigned)(acc[0] >> 32))) * eh;

        pbuf[(t + 1) & 1][k] = v;            // write RAW (normalization deferred)

        float wm = warp_max_pos(v);          // consumed only next step
        if (lane == 0) wred[t & 1][w] = wm;
        __syncthreads();                     // the ONLY barrier per step

        float mx = fmaxf(fmaxf(wred[t & 1][0], wred[t & 1][1]),
                         fmaxf(wred[t & 1][2], wred[t & 1][3]));
        rinv = 1.0f / mx;                    // off critical path
        pend = __logf(mx);

        eh = ehnext;
    }

    // out[b] = C + log( sum_k p_raw[k] * E[EOS,k] )  (last pend/rinv discarded)
    __syncthreads();
    float val = pbuf[t & 1][k] * g_E[EOSI * Kq + k];
    #pragma unroll
    for (int o = 16; o > 0; o >>= 1)
        val += __shfl_xor_sync(0xffffffffu, val, o);
    if (lane == 0) wred[0][w] = val;
    __syncthreads();
    if (k == 0)
        out[b] = C + __logf(wred[0][0] + wred[0][1] + wred[0][2] + wred[0][3]);
}

extern "C" void kernel_launch(void* const* d_in, const int* in_sizes, int n_in,
                              void* d_out, int out_size) {
    const float* h     = (const float*)d_in[0];
    const float* trans = (const float*)d_in[1];
    const float* mask  = (const float*)d_in[2];
    float* out = (float*)d_out;
    (void)in_sizes; (void)n_in; (void)out_size;

    prep_kernel<<<65, 256>>>(trans, mask);
    crf_main_kernel<<<Bq, Kq>>>(h, mask, out);
}

// round 6
// speedup vs baseline: 1.5148x; 1.1288x over previous
#include <cuda_runtime.h>
#include <cuda_bf16.h>

#define Bq 256
#define Tq 512
#define Kq 128
#define SOS 0
#define EOSI 1
#define NSM 152   // GB300 SMs; wave-2 CTA (bid+152) co-resides with bid

__device__ float g_E[Kq * Kq];   // exp(trans), row-major
__device__ int   g_perm[Bq];     // batch index sorted by descending length
__device__ int   g_len[Bq];      // sequence length per batch

// ---------------- prep: E = exp(trans), lengths, rank permutation ----------------
__global__ void prep_kernel(const float* __restrict__ trans,
                            const float* __restrict__ mask) {
    if (blockIdx.x < 64) {
        int i = blockIdx.x * 256 + threadIdx.x;
        g_E[i] = expf(trans[i]);          // exp(-10000) -> exactly 0
    } else {
        __shared__ int slen[Bq];
        int tid = threadIdx.x, w = tid >> 5, lane = tid & 31;
        for (int r = w; r < Bq; r += 8) {
            float s = 0.f;
            const float* mr = mask + (size_t)r * Tq;
            for (int i = lane; i < Tq; i += 32) s += mr[i];
            #pragma unroll
            for (int o = 16; o > 0; o >>= 1) s += __shfl_xor_sync(0xffffffffu, s, o);
            if (lane == 0) slen[r] = (int)(s + 0.5f);
        }
        __syncthreads();
        int L = slen[tid];
        g_len[tid] = L;
        int rank = 0;
        for (int j = 0; j < Bq; j++) {
            int Lj = slen[j];
            rank += (Lj > L) || (Lj == L && j < tid);
        }
        g_perm[rank] = tid;
    }
}

__device__ __forceinline__ unsigned long long pk2(float a, float b) {
    return (unsigned long long)__float_as_uint(a) |
           ((unsigned long long)__float_as_uint(b) << 32);
}
__device__ __forceinline__ void fma2(unsigned long long& d,
                                     unsigned long long a, unsigned long long b) {
    asm("fma.rn.f32x2 %0, %1, %2, %0;" : "+l"(d) : "l"(a), "l"(b));
}
__device__ __forceinline__ void add2(unsigned long long& d, unsigned long long a) {
    asm("add.rn.f32x2 %0, %0, %1;" : "+l"(d) : "l"(a));
}
__device__ __forceinline__ float warp_max_pos(float v) {
    unsigned u = __float_as_uint(v), r;
    asm("redux.sync.max.u32 %0, %1, 0xffffffff;" : "=r"(r) : "r"(u));
    return __uint_as_float(r);     // valid for non-negative floats
}

// ---------------- main CRF scan: 128 threads, 1 thread per output row ----------------
__global__ void __launch_bounds__(128, 2) crf_main_kernel(
    const float* __restrict__ h, float* __restrict__ out)
{
    int bid = blockIdx.x;
    // Solo SMs (bids 104..151, no wave-2 partner) take the 48 longest
    // sequences; pair (i, i+152) takes complementary length ranks.
    int rank;
    if (bid >= 104 && bid < NSM) rank = bid - 104;          // ranks 0..47 solo
    else if (bid < 104)          rank = 48 + bid;           // 48..151
    else                         rank = 407 - bid;          // 255..152
    int b = g_perm[rank] & (Bq - 1);
    int L = g_len[b];

    int k = threadIdx.x;
    int lane = k & 31, w = k >> 5;

    __shared__ __align__(16) float pbuf[2][Kq];
    __shared__ float wred[2][4];

    // thread k owns E row k in registers, packed for f32x2
    unsigned long long e2[Kq / 2];
    {
        const float4* er = reinterpret_cast<const float4*>(g_E + k * Kq);
        #pragma unroll
        for (int i = 0; i < Kq / 4; i++) {
            float4 f = er[i];
            e2[2 * i]     = pk2(f.x, f.y);
            e2[2 * i + 1] = pk2(f.z, f.w);
        }
    }

    pbuf[0][k] = (k == SOS) ? 1.0f : 0.0f;
    float C = 0.0f;          // applied log-offset
    float rinv = 1.0f;       // pending 1/mx
    float pend = 0.0f;       // pending log(mx)

    const float* hb = h + (size_t)b * Tq * Kq + k;

    // 4-deep register prefetch (STATIC names -> no spill), distance-4 MLP
    float h0 = hb[0];
    float h1 = (1 < Tq) ? hb[(size_t)1 * Kq] : 0.f;
    float h2 = (2 < Tq) ? hb[(size_t)2 * Kq] : 0.f;
    float h3 = (3 < Tq) ? hb[(size_t)3 * Kq] : 0.f;
    float eh = __expf(h0);
    __syncthreads();

    int t = 0;

    // one scan step; hcur consumed, hslot refilled with step t+4, ehnext from hnxt
#define STEP(HSLOT, HNXT)                                                        \
    {                                                                            \
        int tp = t + 4;                                                          \
        float hnew = (tp < Tq) ? hb[(size_t)tp * Kq] : 0.f;                      \
        float ehnext = __expf(HNXT);                                             \
        eh *= rinv;                                                              \
        C  += pend;                                                              \
        unsigned long long acc0 = 0, acc1 = 0, acc2 = 0, acc3 = 0,               \
                           acc4 = 0, acc5 = 0, acc6 = 0, acc7 = 0;               \
        const ulonglong2* pu =                                                   \
            reinterpret_cast<const ulonglong2*>(pbuf[t & 1]);                    \
        _Pragma("unroll")                                                        \
        for (int i = 0; i < 16; i++) {                                           \
            ulonglong2 qa = pu[2 * i];                                           \
            ulonglong2 qb = pu[2 * i + 1];                                       \
            fma2(acc0, e2[4 * i],     qa.x);                                     \
            fma2(acc1, e2[4 * i + 1], qa.y);                                     \
            fma2(acc2, e2[4 * i + 2], qb.x);                                     \
            fma2(acc3, e2[4 * i + 3], qb.y);                                     \
            acc4 = acc0; acc5 = acc1; acc6 = acc2; acc7 = acc3;                  \
        }                                                                        \
        add2(acc0, acc2); add2(acc1, acc3);                                      \
        add2(acc0, acc1);                                                        \
        float v = (__uint_as_float((unsigned)acc0) +                             \
                   __uint_as_float((unsigned)(acc0 >> 32))) * eh;                \
        pbuf[(t + 1) & 1][k] = v;                                                \
        float wm = warp_max_pos(v);                                              \
        if (lane == 0) wred[t & 1][w] = wm;                                      \
        __syncthreads();                                                         \
        float mx = fmaxf(fmaxf(wred[t & 1][0], wred[t & 1][1]),                  \
                         fmaxf(wred[t & 1][2], wred[t & 1][3]));                 \
        rinv = 1.0f / mx;                                                        \
        pend = __logf(mx);                                                       \
        HSLOT = hnew;                                                            \
        eh = ehnext;                                                             \
        t++;                                                                     \
    }

    // NOTE: acc4..7 above are dead copies eliminated by the compiler; the
    // live reduction uses 4 independent FMA chains (depth 32 each, ample ILP).
    while (t < L) {
        STEP(h0, h1); if (t >= L) break;
        STEP(h1, h2); if (t >= L) break;
        STEP(h2, h3); if (t >= L) break;
        STEP(h3, h0);
    }
#undef STEP

    // out[b] = C + log( sum_k p_raw[k] * E[EOS,k] )  (last pend/rinv discarded)
    __syncthreads();
    float val = pbuf[t & 1][k] * g_E[EOSI * Kq + k];
    #pragma unroll
    for (int o = 16; o > 0; o >>= 1)
        val += __shfl_xor_sync(0xffffffffu, val, o);
    if (lane == 0) wred[0][w] = val;
    __syncthreads();
    if (k == 0)
        out[b] = C + __logf(wred[0][0] + wred[0][1] + wred[0][2] + wred[0][3]);
}

extern "C" void kernel_launch(void* const* d_in, const int* in_sizes, int n_in,
                              void* d_out, int out_size) {
    const float* h     = (const float*)d_in[0];
    const float* trans = (const float*)d_in[1];
    const float* mask  = (const float*)d_in[2];
    float* out = (float*)d_out;
    (void)in_sizes; (void)n_in; (void)out_size;

    prep_kernel<<<65, 256>>>(trans, mask);
    crf_main_kernel<<<Bq, Kq>>>(h, out);
}

// round 7
// speedup vs baseline: 1.9053x; 1.2577x over previous
#include <cuda_runtime.h>
#include <cuda_bf16.h>

#define Bq 256
#define Tq 512
#define Kq 128
#define SOS 0
#define EOSI 1
#define NSM 152   // GB300 SMs; wave-2 CTA (bid+152) co-resides with bid

__device__ float g_E[Kq * Kq];   // exp(trans), row-major
__device__ int   g_perm[Bq];     // batch index sorted by descending length
__device__ int   g_len[Bq];      // sequence length per batch

// ---------------- prep: E = exp(trans), lengths, rank permutation ----------------
__global__ void prep_kernel(const float* __restrict__ trans,
                            const float* __restrict__ mask) {
    if (blockIdx.x < 64) {
        int i = blockIdx.x * 256 + threadIdx.x;
        g_E[i] = expf(trans[i]);          // exp(-10000) -> exactly 0
    } else {
        __shared__ int slen[Bq];
        int tid = threadIdx.x, w = tid >> 5, lane = tid & 31;
        for (int r = w; r < Bq; r += 8) {
            float s = 0.f;
            const float* mr = mask + (size_t)r * Tq;
            for (int i = lane; i < Tq; i += 32) s += mr[i];
            #pragma unroll
            for (int o = 16; o > 0; o >>= 1) s += __shfl_xor_sync(0xffffffffu, s, o);
            if (lane == 0) slen[r] = (int)(s + 0.5f);
        }
        __syncthreads();
        int L = slen[tid];
        g_len[tid] = L;
        int rank = 0;
        for (int j = 0; j < Bq; j++) {
            int Lj = slen[j];
            rank += (Lj > L) || (Lj == L && j < tid);
        }
        g_perm[rank] = tid;
    }
}

__device__ __forceinline__ unsigned long long pk2(float a, float b) {
    return (unsigned long long)__float_as_uint(a) |
           ((unsigned long long)__float_as_uint(b) << 32);
}
__device__ __forceinline__ void fma2(unsigned long long& d,
                                     unsigned long long a, unsigned long long b) {
    asm("fma.rn.f32x2 %0, %1, %2, %0;" : "+l"(d) : "l"(a), "l"(b));
}
__device__ __forceinline__ void add2(unsigned long long& d, unsigned long long a) {
    asm("add.rn.f32x2 %0, %0, %1;" : "+l"(d) : "l"(a));
}
__device__ __forceinline__ float warp_max_pos(float v) {
    unsigned u = __float_as_uint(v), r;
    asm("redux.sync.max.u32 %0, %1, 0xffffffff;" : "=r"(r) : "r"(u));
    return __uint_as_float(r);     // valid for non-negative floats
}

// ---------------- main CRF scan: 128 threads, 1 thread per output row ----------------
__global__ void __launch_bounds__(128, 2) crf_main_kernel(
    const float* __restrict__ h, float* __restrict__ out)
{
    int bid = blockIdx.x;
    // Solo SMs (bids 104..151, no wave-2 partner) take the 48 longest
    // sequences; pair (i, i+152) takes complementary length ranks.
    int rank;
    if (bid >= 104 && bid < NSM) rank = bid - 104;          // ranks 0..47 solo
    else if (bid < 104)          rank = 48 + bid;           // 48..151
    else                         rank = 407 - bid;          // 255..152
    int b = g_perm[rank] & (Bq - 1);
    int L = g_len[b];

    int k = threadIdx.x;
    int lane = k & 31, w = k >> 5;

    __shared__ __align__(16) float pbuf[2][Kq];
    __shared__ __align__(16) float wred4[4][4];   // max-slots, consumed 2 steps later

    // thread k owns E row k in registers, packed for f32x2
    unsigned long long e2[Kq / 2];
    {
        const float4* er = reinterpret_cast<const float4*>(g_E + k * Kq);
        #pragma unroll
        for (int i = 0; i < Kq / 4; i++) {
            float4 f = er[i];
            e2[2 * i]     = pk2(f.x, f.y);
            e2[2 * i + 1] = pk2(f.z, f.w);
        }
    }

    pbuf[0][k] = (k == SOS) ? 1.0f : 0.0f;
    if (k < 4) { wred4[2][k] = 1.0f; wred4[3][k] = 1.0f; }  // mx for t=0,1 reads
    float C = 0.0f;

    const float* hb = h + (size_t)b * Tq * Kq + k;
    float ehc = __expf(hb[0]);                 // exp(h_0)
    float hy  = (1 < Tq) ? hb[(size_t)1 * Kq] : 0.f;   // h_1
    float hx  = 0.f;
    __syncthreads();

    int t = 0;

    // One scan step. LOADR receives h[t+2]; EXPR holds h[t+1] (exp'd here).
#define STEP(LOADR, EXPR)                                                        \
    {                                                                            \
        int tp = t + 2;                                                          \
        LOADR = (tp < Tq) ? hb[(size_t)tp * Kq] : 0.f;                           \
        float ehn = __expf(EXPR);                                                \
        /* off-path: normalization deferred from step t-2 */                     \
        float4 wv = *reinterpret_cast<const float4*>(wred4[(t - 2) & 3]);        \
        float mx = fmaxf(fmaxf(wv.x, wv.y), fmaxf(wv.z, wv.w));                  \
        float ef = __fdividef(ehc, mx);                                          \
        C += __logf(mx);                                                         \
        unsigned long long acc0 = 0, acc1 = 0, acc2 = 0, acc3 = 0,               \
                           acc4 = 0, acc5 = 0, acc6 = 0, acc7 = 0;               \
        const ulonglong2* pu =                                                   \
            reinterpret_cast<const ulonglong2*>(pbuf[t & 1]);                    \
        _Pragma("unroll")                                                        \
        for (int i = 0; i < 16; i++) {                                           \
            ulonglong2 qa = pu[2 * i];                                           \
            ulonglong2 qb = pu[2 * i + 1];                                       \
            fma2(acc0, e2[4 * i],     qa.x);                                     \
            fma2(acc1, e2[4 * i + 1], qa.y);                                     \
            fma2(acc2, e2[4 * i + 2], qb.x);                                     \
            fma2(acc3, e2[4 * i + 3], qb.y);                                     \
            (void)acc4; (void)acc5; (void)acc6; (void)acc7;                      \
        }                                                                        \
        add2(acc0, acc2); add2(acc1, acc3);                                      \
        add2(acc0, acc1);                                                        \
        float v = (__uint_as_float((unsigned)acc0) +                             \
                   __uint_as_float((unsigned)(acc0 >> 32))) * ef;                \
        pbuf[(t + 1) & 1][k] = v;                                                \
        float wm = warp_max_pos(v);                                              \
        if (lane == 0) wred4[t & 3][w] = wm;                                     \
        __syncthreads();                                                         \
        ehc = ehn;                                                               \
        t++;                                                                     \
    }

    while (t + 2 <= L) {
        STEP(hx, hy);    // step t:   loads h[t+2] into hx, exps hy=h[t+1]
        STEP(hy, hx);    // step t+1: loads h[t+3] into hy, exps hx=h[t+2]
    }
    if (t < L) STEP(hx, hy);
#undef STEP

    // out[b] = C + log( sum_k p_raw[k] * E[EOS,k] )
    // (mx from the last two steps is intentionally never consumed)
    float val = pbuf[t & 1][k] * g_E[EOSI * Kq + k];
    #pragma unroll
    for (int o = 16; o > 0; o >>= 1)
        val += __shfl_xor_sync(0xffffffffu, val, o);
    if (lane == 0) wred4[0][w] = val;
    __syncthreads();
    if (k == 0)
        out[b] = C + __logf(wred4[0][0] + wred4[0][1] + wred4[0][2] + wred4[0][3]);
}

extern "C" void kernel_launch(void* const* d_in, const int* in_sizes, int n_in,
                              void* d_out, int out_size) {
    const float* h     = (const float*)d_in[0];
    const float* trans = (const float*)d_in[1];
    const float* mask  = (const float*)d_in[2];
    float* out = (float*)d_out;
    (void)in_sizes; (void)n_in; (void)out_size;

    prep_kernel<<<65, 256>>>(trans, mask);
    crf_main_kernel<<<Bq, Kq>>>(h, out);
}